// round 1
// baseline (speedup 1.0000x reference)
#include <cuda_runtime.h>
#include <cuda_bf16.h>

// ZBL repulsion energy: per-pair 4-term exponential screening, scatter-add to atoms.
// Inputs (metadata order):
//  0: N (scalar)        1: Zf [N] f32      2: rij [P] f32      3: cutoff_values [P] f32
//  4: idx_i [P] i32     5: idx_j [P] i32   6: adiv [1]         7: apow [1]
//  8..11: c1..c4 [1]    12..15: a1..a4 [1]
// Output: f32 [N]

#define NA_MAX 500000

// scratch: per-atom (z, Zf) packed so both gathers are one 8B load (4MB -> L2 resident)
__device__ float2 g_zzf[NA_MAX];
// derived scalar params:
// [0]=sp(adiv) [1]=sp(apow) [2..5]=KEHALF*c_k_normalized [6..9]=sp(a_k)
__device__ float g_par[12];

__device__ __forceinline__ float softplus_accurate(float x) {
    // accurate softplus; only used in the 1-thread prep kernel
    return log1pf(expf(x));
}

__global__ void prep_kernel(const float* __restrict__ adiv, const float* __restrict__ apow,
                            const float* __restrict__ c1, const float* __restrict__ c2,
                            const float* __restrict__ c3, const float* __restrict__ c4,
                            const float* __restrict__ a1, const float* __restrict__ a2,
                            const float* __restrict__ a3, const float* __restrict__ a4) {
    const float KEHALF = 7.199822675975274f;
    float c1p = softplus_accurate(c1[0]);
    float c2p = softplus_accurate(c2[0]);
    float c3p = softplus_accurate(c3[0]);
    float c4p = softplus_accurate(c4[0]);
    float inv_csum = KEHALF / (c1p + c2p + c3p + c4p);
    g_par[0] = softplus_accurate(adiv[0]);
    g_par[1] = softplus_accurate(apow[0]);
    g_par[2] = c1p * inv_csum;
    g_par[3] = c2p * inv_csum;
    g_par[4] = c3p * inv_csum;
    g_par[5] = c4p * inv_csum;
    g_par[6] = softplus_accurate(a1[0]);
    g_par[7] = softplus_accurate(a2[0]);
    g_par[8] = softplus_accurate(a3[0]);
    g_par[9] = softplus_accurate(a4[0]);
}

__global__ void atoms_kernel(const float* __restrict__ Zf, float* __restrict__ out, int n) {
    int i = blockIdx.x * blockDim.x + threadIdx.x;
    if (i < n) {
        float spapow = g_par[1];
        float Z = Zf[i];
        // z = Z^sp(apow); Z in [1, 94] so log2 path is well-conditioned
        float z = exp2f(spapow * __log2f(Z));
        g_zzf[i] = make_float2(z, Z);
        out[i] = 0.0f;  // d_out is poisoned by the harness
    }
}

__global__ void __launch_bounds__(256) pairs_kernel(
    const float* __restrict__ rij, const float* __restrict__ cv,
    const int* __restrict__ idx_i, const int* __restrict__ idx_j,
    float* __restrict__ out, int npairs) {
    int q = blockIdx.x * blockDim.x + threadIdx.x;
    int base = q * 4;
    if (base >= npairs) return;

    const float spadiv = g_par[0];
    const float k1 = g_par[2], k2 = g_par[3], k3 = g_par[4], k4 = g_par[5];
    const float s1 = g_par[6], s2 = g_par[7], s3 = g_par[8], s4 = g_par[9];

    float r[4], c[4];
    int ia[4], ja[4];
    int cnt;
    if (base + 4 <= npairs) {
        // vector path
        float4 r4 = *reinterpret_cast<const float4*>(rij + base);
        float4 c4 = *reinterpret_cast<const float4*>(cv + base);
        int4 i4 = *reinterpret_cast<const int4*>(idx_i + base);
        int4 j4 = *reinterpret_cast<const int4*>(idx_j + base);
        r[0] = r4.x; r[1] = r4.y; r[2] = r4.z; r[3] = r4.w;
        c[0] = c4.x; c[1] = c4.y; c[2] = c4.z; c[3] = c4.w;
        ia[0] = i4.x; ia[1] = i4.y; ia[2] = i4.z; ia[3] = i4.w;
        ja[0] = j4.x; ja[1] = j4.y; ja[2] = j4.z; ja[3] = j4.w;
        cnt = 4;
    } else {
        cnt = npairs - base;
        for (int k = 0; k < cnt; k++) {
            r[k] = rij[base + k];
            c[k] = cv[base + k];
            ia[k] = idx_i[base + k];
            ja[k] = idx_j[base + k];
        }
    }

#pragma unroll
    for (int k = 0; k < 4; k++) {
        if (k >= cnt) break;
        float2 zi = g_zzf[ia[k]];
        float2 zj = g_zzf[ja[k]];
        float a = (zi.x + zj.x) * spadiv;
        float t = -a * r[k];
        float f = k1 * __expf(s1 * t)
                + k2 * __expf(s2 * t)
                + k3 * __expf(s3 * t)
                + k4 * __expf(s4 * t);
        float contrib = __fdividef(f * c[k] * zi.y * zj.y, r[k]);
        atomicAdd(&out[ia[k]], contrib);
    }
}

extern "C" void kernel_launch(void* const* d_in, const int* in_sizes, int n_in,
                              void* d_out, int out_size) {
    const float* Zf    = (const float*)d_in[1];
    const float* rij   = (const float*)d_in[2];
    const float* cvv   = (const float*)d_in[3];
    const int*   idx_i = (const int*)d_in[4];
    const int*   idx_j = (const int*)d_in[5];
    const float* adiv  = (const float*)d_in[6];
    const float* apow  = (const float*)d_in[7];
    const float* c1    = (const float*)d_in[8];
    const float* c2    = (const float*)d_in[9];
    const float* c3    = (const float*)d_in[10];
    const float* c4    = (const float*)d_in[11];
    const float* a1    = (const float*)d_in[12];
    const float* a2    = (const float*)d_in[13];
    const float* a3    = (const float*)d_in[14];
    const float* a4    = (const float*)d_in[15];

    int n = in_sizes[1];
    int p = in_sizes[2];
    float* out = (float*)d_out;

    prep_kernel<<<1, 1>>>(adiv, apow, c1, c2, c3, c4, a1, a2, a3, a4);

    int ab = (n + 255) / 256;
    atoms_kernel<<<ab, 256>>>(Zf, out, n);

    int nthreads = (p + 3) / 4;
    int pb = (nthreads + 255) / 256;
    pairs_kernel<<<pb, 256>>>(rij, cvv, idx_i, idx_j, out, p);
}